// round 15
// baseline (speedup 1.0000x reference)
#include <cuda_runtime.h>
#include <cuda_fp16.h>
#include <cstdint>

#define D_MODEL 1024
#define NHEAD   16
#define HDIM    64
#define BATCH   4
#define SEQ     2048
#define NTOK    (BATCH*SEQ)

#define ACT_N ((size_t)NTOK * D_MODEL)
#define W_N   ((size_t)D_MODEL * D_MODEL)

// Scratch (allocation-free per harness rules) — all fp16
__device__ __half g_qin[ACT_N], g_kin[ACT_N], g_vin[ACT_N];
__device__ __half g_Wqh[W_N], g_Wql[W_N], g_Wkh[W_N], g_Wkl[W_N];
__device__ __half g_Wvh[W_N], g_Wvl[W_N], g_Woh[W_N], g_Wol[W_N];
__device__ __half g_Qp[ACT_N];                 // scaled by log2(e)/8
__device__ __half g_Kph[ACT_N], g_Kpl[ACT_N];  // split hi/lo
__device__ __half g_Vp[ACT_N];
__device__ __half g_Att[ACT_N];

// ---------------------------------------------------------------------------
// helpers
// ---------------------------------------------------------------------------
__device__ __forceinline__ uint32_t smem_u32(const void* p) {
    uint32_t a;
    asm("{ .reg .u64 t; cvta.to.shared.u64 t, %1; cvt.u32.u64 %0, t; }"
        : "=r"(a) : "l"(p));
    return a;
}
__device__ __forceinline__ void ldm_x4(uint32_t r[4], uint32_t addr) {
    asm volatile("ldmatrix.sync.aligned.m8n8.x4.shared.b16 {%0,%1,%2,%3}, [%4];"
                 : "=r"(r[0]), "=r"(r[1]), "=r"(r[2]), "=r"(r[3]) : "r"(addr));
}
__device__ __forceinline__ void ldm_x4_t(uint32_t r[4], uint32_t addr) {
    asm volatile("ldmatrix.sync.aligned.m8n8.x4.trans.shared.b16 {%0,%1,%2,%3}, [%4];"
                 : "=r"(r[0]), "=r"(r[1]), "=r"(r[2]), "=r"(r[3]) : "r"(addr));
}
__device__ __forceinline__ void mma16816h(float c[4], const uint32_t a[4],
                                          uint32_t b0, uint32_t b1) {
    asm volatile(
        "mma.sync.aligned.m16n8k16.row.col.f32.f16.f16.f32 "
        "{%0,%1,%2,%3}, {%4,%5,%6,%7}, {%8,%9}, {%0,%1,%2,%3};"
        : "+f"(c[0]), "+f"(c[1]), "+f"(c[2]), "+f"(c[3])
        : "r"(a[0]), "r"(a[1]), "r"(a[2]), "r"(a[3]), "r"(b0), "r"(b1));
}
__device__ __forceinline__ void split2h(float f0, float f1,
                                        uint32_t& hi, uint32_t& lo) {
    __half2 h = __floats2half2_rn(f0, f1);
    float2 hf = __half22float2(h);
    __half2 l = __floats2half2_rn(f0 - hf.x, f1 - hf.y);
    hi = *(uint32_t*)&h; lo = *(uint32_t*)&l;
}
__device__ __forceinline__ uint32_t pack2h(float f0, float f1) {
    __half2 h = __floats2half2_rn(f0, f1);
    return *(uint32_t*)&h;
}
__device__ __forceinline__ void cp16(uint32_t dst, const void* src) {
    asm volatile("cp.async.cg.shared.global [%0], [%1], 16;"
                 :: "r"(dst), "l"(src) : "memory");
}
__device__ __forceinline__ void cp_commit() {
    asm volatile("cp.async.commit_group;" ::: "memory");
}
#define CP_WAIT(n) asm volatile("cp.async.wait_group %0;" :: "n"(n) : "memory")

// ------------------------- producer conversion kernels ----------------------
__global__ void cvt_f16(const float* __restrict__ x0, __half* __restrict__ y0,
                        const float* __restrict__ x1, __half* __restrict__ y1,
                        const float* __restrict__ x2, __half* __restrict__ y2,
                        int n4)
{
    const float* x = (blockIdx.z == 0) ? x0 : (blockIdx.z == 1) ? x1 : x2;
    __half*      y = (blockIdx.z == 0) ? y0 : (blockIdx.z == 1) ? y1 : y2;
    int i = blockIdx.x * blockDim.x + threadIdx.x;
    int stride = gridDim.x * blockDim.x;
    for (; i < n4; i += stride) {
        float4 v = ((const float4*)x)[i];
        uint2 r;
        r.x = pack2h(v.x, v.y);
        r.y = pack2h(v.z, v.w);
        ((uint2*)y)[i] = r;
    }
}

__global__ void wsplit_f16(const float* __restrict__ x0, __half* __restrict__ h0, __half* __restrict__ l0,
                           const float* __restrict__ x1, __half* __restrict__ h1, __half* __restrict__ l1,
                           const float* __restrict__ x2, __half* __restrict__ h2, __half* __restrict__ l2,
                           const float* __restrict__ x3, __half* __restrict__ h3, __half* __restrict__ l3,
                           int n4)
{
    int z = blockIdx.z;
    const float* x = (z == 0) ? x0 : (z == 1) ? x1 : (z == 2) ? x2 : x3;
    __half*     yh = (z == 0) ? h0 : (z == 1) ? h1 : (z == 2) ? h2 : h3;
    __half*     yl = (z == 0) ? l0 : (z == 1) ? l1 : (z == 2) ? l2 : l3;
    int i = blockIdx.x * blockDim.x + threadIdx.x;
    int stride = gridDim.x * blockDim.x;
    for (; i < n4; i += stride) {
        float4 v = ((const float4*)x)[i];
        uint2 h, l;
        split2h(v.x, v.y, h.x, l.x);
        split2h(v.z, v.w, h.y, l.y);
        ((uint2*)yh)[i] = h;
        ((uint2*)yl)[i] = l;
    }
}

// ---------------------------------------------------------------------------
// GEMM: C[8192,1024] = A @ W^T + bias — fp16 2-pass, all-fp16 inputs,
// register-prefetch double buffer (R12 winner, verbatim).
// Epilogue mode = base_mode + z:
//   0: fp32 out   1: fp16 scaled log2e/8 [Q]   2: fp16 split hi/lo [K]
//   3: fp16 [V]
// ---------------------------------------------------------------------------
#define GT_B    18432
#define GSTG_B  (3 * GT_B)
#define GSM_B   (2 * GSTG_B)         // 110592

#define QSCALE  0.18033688f   // 0.125 * log2(e)

__global__ __launch_bounds__(256, 1)
void gemm_f16(const __half* __restrict__ A0, const __half* __restrict__ Wh0,
              const __half* __restrict__ Wl0, const float* __restrict__ b0_,
              void* O0a, void* O0b,
              const __half* __restrict__ A1, const __half* __restrict__ Wh1,
              const __half* __restrict__ Wl1, const float* __restrict__ b1_,
              void* O1a, void* O1b,
              const __half* __restrict__ A2, const __half* __restrict__ Wh2,
              const __half* __restrict__ Wl2, const float* __restrict__ b2_,
              void* O2a, void* O2b,
              int base_mode)
{
    extern __shared__ char sm[];
    const uint32_t s0 = smem_u32(sm);

    const int z = blockIdx.z;
    const __half* A    = (z == 0) ? A0  : (z == 1) ? A1  : A2;
    const __half* Wh   = (z == 0) ? Wh0 : (z == 1) ? Wh1 : Wh2;
    const __half* Wl   = (z == 0) ? Wl0 : (z == 1) ? Wl1 : Wl2;
    const float*  bias = (z == 0) ? b0_ : (z == 1) ? b1_ : b2_;
    void* Oa = (z == 0) ? O0a : (z == 1) ? O1a : O2a;
    void* Ob = (z == 0) ? O0b : (z == 1) ? O1b : O2b;
    const int mode = base_mode + z;

    const int tid  = threadIdx.x;
    const int lane = tid & 31;
    const int wid  = tid >> 5;
    const int bm = blockIdx.y * 128;
    const int bn = blockIdx.x * 128;
    const int wm = (wid >> 2) * 64;
    const int wn = (wid & 3) * 32;

    float acc[4][4][4];
#pragma unroll
    for (int i = 0; i < 4; i++)
#pragma unroll
        for (int j = 0; j < 4; j++)
#pragma unroll
            for (int q = 0; q < 4; q++) acc[i][j][q] = 0.f;

    const uint32_t offA = (uint32_t)(lane & 15) * 144 + (uint32_t)(lane >> 4) * 16;
    const uint32_t offB = (uint32_t)((lane & 7) + ((lane >> 4) & 1) * 8) * 144
                        + (uint32_t)((lane >> 3) & 1) * 16;

    uint4 aw[4], whw[4], wlw[4];
#pragma unroll
    for (int j = 0; j < 4; j++) {
        int c = tid + j * 256;
        int row = c >> 3, seg = c & 7;
        aw[j]  = *(const uint4*)(A  + (size_t)(bm + row) * D_MODEL + seg * 8);
        whw[j] = *(const uint4*)(Wh + (size_t)(bn + row) * D_MODEL + seg * 8);
        wlw[j] = *(const uint4*)(Wl + (size_t)(bn + row) * D_MODEL + seg * 8);
    }
    {
        char* stg = sm;
#pragma unroll
        for (int j = 0; j < 4; j++) {
            int c = tid + j * 256;
            int row = c >> 3, seg = c & 7;
            uint32_t ad = (uint32_t)(row * 144 + seg * 16);
            *(uint4*)(stg + 0 * GT_B + ad) = aw[j];
            *(uint4*)(stg + 1 * GT_B + ad) = whw[j];
            *(uint4*)(stg + 2 * GT_B + ad) = wlw[j];
        }
    }
    __syncthreads();

    for (int kt = 0; kt < 16; kt++) {
        if (kt < 15) {
            const int k0 = (kt + 1) * 64;
#pragma unroll
            for (int j = 0; j < 4; j++) {
                int c = tid + j * 256;
                int row = c >> 3, seg = c & 7;
                aw[j]  = *(const uint4*)(A  + (size_t)(bm + row) * D_MODEL + k0 + seg * 8);
                whw[j] = *(const uint4*)(Wh + (size_t)(bn + row) * D_MODEL + k0 + seg * 8);
                wlw[j] = *(const uint4*)(Wl + (size_t)(bn + row) * D_MODEL + k0 + seg * 8);
            }
        }

        const uint32_t sb  = s0 + (uint32_t)(kt & 1) * GSTG_B;
        const uint32_t sA  = sb;
        const uint32_t sWh = sb + 1 * GT_B;
        const uint32_t sWl = sb + 2 * GT_B;

#pragma unroll
        for (int ks = 0; ks < 4; ks++) {
            uint32_t ah[4][4], wh[2][4], wl[2][4];
            const uint32_t ka = (uint32_t)ks * 32;
#pragma unroll
            for (int mt = 0; mt < 4; mt++) {
                uint32_t ra = (uint32_t)((wm + mt * 16) * 144) + offA + ka;
                ldm_x4(ah[mt], sA + ra);
            }
#pragma unroll
            for (int p = 0; p < 2; p++) {
                uint32_t rb = (uint32_t)((wn + p * 16) * 144) + offB + ka;
                ldm_x4(wh[p], sWh + rb);
                ldm_x4(wl[p], sWl + rb);
            }
#pragma unroll
            for (int mt = 0; mt < 4; mt++)
#pragma unroll
                for (int nt = 0; nt < 4; nt++) {
                    uint32_t h0 = wh[nt >> 1][(nt & 1) * 2];
                    uint32_t h1 = wh[nt >> 1][(nt & 1) * 2 + 1];
                    uint32_t l0 = wl[nt >> 1][(nt & 1) * 2];
                    uint32_t l1 = wl[nt >> 1][(nt & 1) * 2 + 1];
                    mma16816h(acc[mt][nt], ah[mt], h0, h1);
                    mma16816h(acc[mt][nt], ah[mt], l0, l1);
                }
        }

        if (kt < 15) {
            char* stg = sm + ((kt + 1) & 1) * GSTG_B;
#pragma unroll
            for (int j = 0; j < 4; j++) {
                int c = tid + j * 256;
                int row = c >> 3, seg = c & 7;
                uint32_t ad = (uint32_t)(row * 144 + seg * 16);
                *(uint4*)(stg + 0 * GT_B + ad) = aw[j];
                *(uint4*)(stg + 1 * GT_B + ad) = whw[j];
                *(uint4*)(stg + 2 * GT_B + ad) = wlw[j];
            }
        }
        __syncthreads();
    }

#pragma unroll
    for (int mt = 0; mt < 4; mt++) {
        int row0 = bm + wm + mt * 16 + (lane >> 2);
#pragma unroll
        for (int nt = 0; nt < 4; nt++) {
            int col = bn + wn + nt * 8 + (lane & 3) * 2;
            float2 b2 = *(const float2*)&bias[col];
            float c0 = acc[mt][nt][0] + b2.x, c1 = acc[mt][nt][1] + b2.y;
            float c2 = acc[mt][nt][2] + b2.x, c3 = acc[mt][nt][3] + b2.y;
            size_t i0 = (size_t)row0 * D_MODEL + col;
            size_t i1 = (size_t)(row0 + 8) * D_MODEL + col;
            if (mode == 0) {
                *(float2*)((float*)Oa + i0) = make_float2(c0, c1);
                *(float2*)((float*)Oa + i1) = make_float2(c2, c3);
            } else if (mode == 1) {       // Q: fp16 scaled log2e/8
                *(uint32_t*)((__half*)Oa + i0) = pack2h(c0 * QSCALE, c1 * QSCALE);
                *(uint32_t*)((__half*)Oa + i1) = pack2h(c2 * QSCALE, c3 * QSCALE);
            } else if (mode == 2) {       // K: split hi/lo
                uint32_t h, l;
                split2h(c0, c1, h, l);
                *(uint32_t*)((__half*)Oa + i0) = h;
                *(uint32_t*)((__half*)Ob + i0) = l;
                split2h(c2, c3, h, l);
                *(uint32_t*)((__half*)Oa + i1) = h;
                *(uint32_t*)((__half*)Ob + i1) = l;
            } else {                       // V: plain fp16
                *(uint32_t*)((__half*)Oa + i0) = pack2h(c0, c1);
                *(uint32_t*)((__half*)Oa + i1) = pack2h(c2, c3);
            }
        }
    }
}

// ---------------------------------------------------------------------------
// Flash attention — R12 math, restructured for occupancy:
// 64 q-rows per CTA (4 warps x 16 rows), grid (SEQ/64, B*H) = (32, 64).
// cp.async 2-stage KV pipeline, exp2-domain softmax.
// smem: Q[64][72]h (9.2KB) + 2 stages of (Kh|Kl|V)[64][72]h = 64.5 KB
// -> up to 3 CTAs/SM (12 warps) if regs allow; finer grid fixes wave tail.
// ---------------------------------------------------------------------------
#define AQ    0
#define AKV0  9216
#define AT    9216
#define AST   (3 * AT)
#define A_SMEM (AKV0 + 2 * AST)       // 64512

__global__ __launch_bounds__(128)
void attn_mma(const __half* __restrict__ Qp, const __half* __restrict__ Kh_,
              const __half* __restrict__ Kl_, const __half* __restrict__ Vp,
              __half* __restrict__ Og)
{
    extern __shared__ char sm[];
    const uint32_t s0 = smem_u32(sm);

    const int tid  = threadIdx.x;
    const int lane = tid & 31;
    const int wid  = tid >> 5;
    const int qt = blockIdx.x;          // 32 q-tiles of 64 rows
    const int bh = blockIdx.y;          // 64 (b,h)
    const int b = bh >> 4, h = bh & 15;

    const size_t tok0 = (size_t)b * SEQ + qt * 64;
    const __half* Qb  = Qp  + tok0 * D_MODEL + h * 64;
    const __half* Khb = Kh_ + (size_t)b * SEQ * D_MODEL + h * 64;
    const __half* Klb = Kl_ + (size_t)b * SEQ * D_MODEL + h * 64;
    const __half* Vb  = Vp  + (size_t)b * SEQ * D_MODEL + h * 64;

    const uint32_t laneA = (uint32_t)(((lane >> 3) & 1) * 8 + (lane & 7)) * 144
                         + (uint32_t)(lane >> 4) * 16;
    const uint32_t laneB = (uint32_t)((lane >> 4) * 8 + (lane & 7)) * 144
                         + (uint32_t)((lane >> 3) & 1) * 16;
    const uint32_t wq = (uint32_t)wid * 16 * 144;   // 16 rows per warp

    auto issue_kv = [&](int kt) {
        const uint32_t sb = s0 + AKV0 + (uint32_t)(kt & 1) * AST;
        const size_t rb = (size_t)kt * 64 * D_MODEL;
#pragma unroll
        for (int j = 0; j < 4; j++) {
            int c = tid + j * 128;
            int row = c >> 3, seg = c & 7;
            size_t go = rb + (size_t)row * D_MODEL + seg * 8;
            uint32_t ad = (uint32_t)(row * 144 + seg * 16);
            cp16(sb + 0 * AT + ad, Khb + go);
            cp16(sb + 1 * AT + ad, Klb + go);
            cp16(sb + 2 * AT + ad, Vb  + go);
        }
        cp_commit();
    };

    // Q tile: 64 rows x 8 segs = 512 chunks / 128 thr = 4 iters
#pragma unroll
    for (int j = 0; j < 4; j++) {
        int c = tid + j * 128;
        int row = c >> 3, seg = c & 7;
        *(uint4*)(sm + AQ + row * 144 + seg * 16) =
            *(const uint4*)(Qb + (size_t)row * D_MODEL + seg * 8);
    }
    issue_kv(0);
    issue_kv(1);

    float o[8][4];
#pragma unroll
    for (int dn = 0; dn < 8; dn++)
#pragma unroll
        for (int q = 0; q < 4; q++) o[dn][q] = 0.f;
    float mrow[2] = {-1e30f, -1e30f};
    float lrow[2] = {0.f, 0.f};

    for (int kt = 0; kt < SEQ / 64; kt++) {
        CP_WAIT(1);
        __syncthreads();

        const uint32_t kb = s0 + AKV0 + (uint32_t)(kt & 1) * AST;

        // ---- S = Q @ K^T (2-pass); scores in log2 domain
        float s[8][4];
#pragma unroll
        for (int nt = 0; nt < 8; nt++)
#pragma unroll
            for (int q = 0; q < 4; q++) s[nt][q] = 0.f;

#pragma unroll
        for (int k = 0; k < 4; k++) {
            uint32_t bhf[4][4], blf[4][4];
#pragma unroll
            for (int np = 0; np < 4; np++) {
                uint32_t rbb = (uint32_t)(np * 16 * 144) + k * 32 + laneB;
                ldm_x4(bhf[np], kb + 0 * AT + rbb);
                ldm_x4(blf[np], kb + 1 * AT + rbb);
            }
            uint32_t ah[4];
            uint32_t ra = wq + k * 32 + laneA;
            ldm_x4(ah, s0 + AQ + ra);
#pragma unroll
            for (int nt = 0; nt < 8; nt++) {
                uint32_t h0 = bhf[nt >> 1][(nt & 1) * 2];
                uint32_t h1 = bhf[nt >> 1][(nt & 1) * 2 + 1];
                uint32_t l0 = blf[nt >> 1][(nt & 1) * 2];
                uint32_t l1 = blf[nt >> 1][(nt & 1) * 2 + 1];
                mma16816h(s[nt], ah, h0, h1);
                mma16816h(s[nt], ah, l0, l1);
            }
        }

        // ---- online softmax (exp2 domain)
        float corr[2];
#pragma unroll
        for (int rr = 0; rr < 2; rr++) {
            int c0 = rr * 2;
            float mx = -1e30f;
#pragma unroll
            for (int nt = 0; nt < 8; nt++)
                mx = fmaxf(mx, fmaxf(s[nt][c0], s[nt][c0 + 1]));
            mx = fmaxf(mx, __shfl_xor_sync(0xffffffffu, mx, 1));
            mx = fmaxf(mx, __shfl_xor_sync(0xffffffffu, mx, 2));
            float mn = fmaxf(mrow[rr], mx);
            corr[rr] = exp2f(mrow[rr] - mn);
            mrow[rr] = mn;
            float rs = 0.f;
#pragma unroll
            for (int nt = 0; nt < 8; nt++) {
                float e0 = exp2f(s[nt][c0] - mn);
                float e1 = exp2f(s[nt][c0 + 1] - mn);
                s[nt][c0] = e0; s[nt][c0 + 1] = e1;
                rs += e0 + e1;
            }
            rs += __shfl_xor_sync(0xffffffffu, rs, 1);
            rs += __shfl_xor_sync(0xffffffffu, rs, 2);
            lrow[rr] = lrow[rr] * corr[rr] + rs;
        }
#pragma unroll
        for (int dn = 0; dn < 8; dn++) {
            o[dn][0] *= corr[0]; o[dn][1] *= corr[0];
            o[dn][2] *= corr[1]; o[dn][3] *= corr[1];
        }

        // ---- O += P @ V (1-pass)
#pragma unroll
        for (int kk = 0; kk < 4; kk++) {
            uint32_t vhf[4][4];
#pragma unroll
            for (int dp = 0; dp < 4; dp++) {
                uint32_t rv = (uint32_t)(kk * 16 * 144) + dp * 32 + laneA;
                ldm_x4_t(vhf[dp], kb + 2 * AT + rv);
            }
            uint32_t ph[4];
            ph[0] = pack2h(s[2 * kk][0],     s[2 * kk][1]);
            ph[1] = pack2h(s[2 * kk][2],     s[2 * kk][3]);
            ph[2] = pack2h(s[2 * kk + 1][0], s[2 * kk + 1][1]);
            ph[3] = pack2h(s[2 * kk + 1][2], s[2 * kk + 1][3]);
#pragma unroll
            for (int dn = 0; dn < 8; dn++) {
                uint32_t h0 = vhf[dn >> 1][(dn & 1) * 2];
                uint32_t h1 = vhf[dn >> 1][(dn & 1) * 2 + 1];
                mma16816h(o[dn], ph, h0, h1);
            }
        }

        __syncthreads();
        if (kt + 2 < SEQ / 64) issue_kv(kt + 2);
    }

    // ---- epilogue: normalize, write fp16 for the Wo GEMM
    float inv0 = 1.f / lrow[0], inv1 = 1.f / lrow[1];
    size_t row0 = tok0 + wid * 16 + (lane >> 2);
#pragma unroll
    for (int dn = 0; dn < 8; dn++) {
        int col = h * 64 + dn * 8 + (lane & 3) * 2;
        *(uint32_t*)(Og + row0 * D_MODEL + col) =
            pack2h(o[dn][0] * inv0, o[dn][1] * inv0);
        *(uint32_t*)(Og + (row0 + 8) * D_MODEL + col) =
            pack2h(o[dn][2] * inv1, o[dn][3] * inv1);
    }
}

// ---------------------------------------------------------------------------
extern "C" void kernel_launch(void* const* d_in, const int* in_sizes, int n_in,
                              void* d_out, int out_size)
{
    const float* q  = (const float*)d_in[0];
    const float* k  = (const float*)d_in[1];
    const float* v  = (const float*)d_in[2];
    const float* Wq = (const float*)d_in[3];
    const float* bq = (const float*)d_in[4];
    const float* Wk = (const float*)d_in[5];
    const float* bk = (const float*)d_in[6];
    const float* Wv = (const float*)d_in[7];
    const float* bv = (const float*)d_in[8];
    const float* Wo = (const float*)d_in[9];
    const float* bo = (const float*)d_in[10];
    float* out = (float*)d_out;

    __half *qin, *kin, *vin;
    __half *Wqh, *Wql, *Wkh, *Wkl, *Wvh, *Wvl, *Woh, *Wol;
    __half *Qp, *Kph, *Kpl, *Vp, *Att;
    cudaGetSymbolAddress((void**)&qin, g_qin);
    cudaGetSymbolAddress((void**)&kin, g_kin);
    cudaGetSymbolAddress((void**)&vin, g_vin);
    cudaGetSymbolAddress((void**)&Wqh, g_Wqh); cudaGetSymbolAddress((void**)&Wql, g_Wql);
    cudaGetSymbolAddress((void**)&Wkh, g_Wkh); cudaGetSymbolAddress((void**)&Wkl, g_Wkl);
    cudaGetSymbolAddress((void**)&Wvh, g_Wvh); cudaGetSymbolAddress((void**)&Wvl, g_Wvl);
    cudaGetSymbolAddress((void**)&Woh, g_Woh); cudaGetSymbolAddress((void**)&Wol, g_Wol);
    cudaGetSymbolAddress((void**)&Qp,  g_Qp);
    cudaGetSymbolAddress((void**)&Kph, g_Kph); cudaGetSymbolAddress((void**)&Kpl, g_Kpl);
    cudaGetSymbolAddress((void**)&Vp,  g_Vp);
    cudaGetSymbolAddress((void**)&Att, g_Att);

    cudaFuncSetAttribute(gemm_f16,
                         cudaFuncAttributeMaxDynamicSharedMemorySize, GSM_B);
    cudaFuncSetAttribute(attn_mma,
                         cudaFuncAttributeMaxDynamicSharedMemorySize, A_SMEM);

    cvt_f16<<<dim3(512, 1, 3), 256>>>(q, qin, k, kin, v, vin, (int)(ACT_N / 4));
    wsplit_f16<<<dim3(256, 1, 4), 256>>>(Wq, Wqh, Wql, Wk, Wkh, Wkl,
                                         Wv, Wvh, Wvl, Wo, Woh, Wol,
                                         (int)(W_N / 4));

    dim3 pgrid(D_MODEL / 128, NTOK / 128, 3);
    gemm_f16<<<pgrid, 256, GSM_B>>>(qin, Wqh, Wql, bq, Qp,  nullptr,
                                    kin, Wkh, Wkl, bk, Kph, Kpl,
                                    vin, Wvh, Wvl, bv, Vp,  nullptr,
                                    1);

    attn_mma<<<dim3(SEQ / 64, BATCH * NHEAD), 128, A_SMEM>>>(Qp, Kph, Kpl, Vp, Att);

    dim3 ogrid(D_MODEL / 128, NTOK / 128, 1);
    gemm_f16<<<ogrid, 256, GSM_B>>>(Att, Woh, Wol, bo, out, nullptr,
                                    Att, Woh, Wol, bo, out, nullptr,
                                    Att, Woh, Wol, bo, out, nullptr,
                                    0);
}

// round 16
// speedup vs baseline: 1.2096x; 1.2096x over previous
#include <cuda_runtime.h>
#include <cuda_fp16.h>
#include <cstdint>

#define D_MODEL 1024
#define NHEAD   16
#define HDIM    64
#define BATCH   4
#define SEQ     2048
#define NTOK    (BATCH*SEQ)

#define ACT_N ((size_t)NTOK * D_MODEL)
#define W_N   ((size_t)D_MODEL * D_MODEL)

// Scratch (allocation-free per harness rules) — all fp16
__device__ __half g_qin[ACT_N], g_kin[ACT_N], g_vin[ACT_N];
__device__ __half g_Wqh[W_N], g_Wql[W_N], g_Wkh[W_N], g_Wkl[W_N];
__device__ __half g_Wvh[W_N], g_Wvl[W_N], g_Woh[W_N], g_Wol[W_N];
__device__ __half g_Qp[ACT_N];                 // scaled by log2(e)/8
__device__ __half g_Kp[ACT_N];                 // single fp16 now
__device__ __half g_Vp[ACT_N];
__device__ __half g_Att[ACT_N];

// ---------------------------------------------------------------------------
// helpers
// ---------------------------------------------------------------------------
__device__ __forceinline__ uint32_t smem_u32(const void* p) {
    uint32_t a;
    asm("{ .reg .u64 t; cvta.to.shared.u64 t, %1; cvt.u32.u64 %0, t; }"
        : "=r"(a) : "l"(p));
    return a;
}
__device__ __forceinline__ void ldm_x4(uint32_t r[4], uint32_t addr) {
    asm volatile("ldmatrix.sync.aligned.m8n8.x4.shared.b16 {%0,%1,%2,%3}, [%4];"
                 : "=r"(r[0]), "=r"(r[1]), "=r"(r[2]), "=r"(r[3]) : "r"(addr));
}
__device__ __forceinline__ void ldm_x4_t(uint32_t r[4], uint32_t addr) {
    asm volatile("ldmatrix.sync.aligned.m8n8.x4.trans.shared.b16 {%0,%1,%2,%3}, [%4];"
                 : "=r"(r[0]), "=r"(r[1]), "=r"(r[2]), "=r"(r[3]) : "r"(addr));
}
__device__ __forceinline__ void mma16816h(float c[4], const uint32_t a[4],
                                          uint32_t b0, uint32_t b1) {
    asm volatile(
        "mma.sync.aligned.m16n8k16.row.col.f32.f16.f16.f32 "
        "{%0,%1,%2,%3}, {%4,%5,%6,%7}, {%8,%9}, {%0,%1,%2,%3};"
        : "+f"(c[0]), "+f"(c[1]), "+f"(c[2]), "+f"(c[3])
        : "r"(a[0]), "r"(a[1]), "r"(a[2]), "r"(a[3]), "r"(b0), "r"(b1));
}
__device__ __forceinline__ void split2h(float f0, float f1,
                                        uint32_t& hi, uint32_t& lo) {
    __half2 h = __floats2half2_rn(f0, f1);
    float2 hf = __half22float2(h);
    __half2 l = __floats2half2_rn(f0 - hf.x, f1 - hf.y);
    hi = *(uint32_t*)&h; lo = *(uint32_t*)&l;
}
__device__ __forceinline__ uint32_t pack2h(float f0, float f1) {
    __half2 h = __floats2half2_rn(f0, f1);
    return *(uint32_t*)&h;
}
__device__ __forceinline__ void cp16(uint32_t dst, const void* src) {
    asm volatile("cp.async.cg.shared.global [%0], [%1], 16;"
                 :: "r"(dst), "l"(src) : "memory");
}
__device__ __forceinline__ void cp_commit() {
    asm volatile("cp.async.commit_group;" ::: "memory");
}
#define CP_WAIT(n) asm volatile("cp.async.wait_group %0;" :: "n"(n) : "memory")

// ------------------------- producer conversion kernels ----------------------
__global__ void cvt_f16(const float* __restrict__ x0, __half* __restrict__ y0,
                        const float* __restrict__ x1, __half* __restrict__ y1,
                        const float* __restrict__ x2, __half* __restrict__ y2,
                        int n4)
{
    const float* x = (blockIdx.z == 0) ? x0 : (blockIdx.z == 1) ? x1 : x2;
    __half*      y = (blockIdx.z == 0) ? y0 : (blockIdx.z == 1) ? y1 : y2;
    int i = blockIdx.x * blockDim.x + threadIdx.x;
    int stride = gridDim.x * blockDim.x;
    for (; i < n4; i += stride) {
        float4 v = ((const float4*)x)[i];
        uint2 r;
        r.x = pack2h(v.x, v.y);
        r.y = pack2h(v.z, v.w);
        ((uint2*)y)[i] = r;
    }
}

__global__ void wsplit_f16(const float* __restrict__ x0, __half* __restrict__ h0, __half* __restrict__ l0,
                           const float* __restrict__ x1, __half* __restrict__ h1, __half* __restrict__ l1,
                           const float* __restrict__ x2, __half* __restrict__ h2, __half* __restrict__ l2,
                           const float* __restrict__ x3, __half* __restrict__ h3, __half* __restrict__ l3,
                           int n4)
{
    int z = blockIdx.z;
    const float* x = (z == 0) ? x0 : (z == 1) ? x1 : (z == 2) ? x2 : x3;
    __half*     yh = (z == 0) ? h0 : (z == 1) ? h1 : (z == 2) ? h2 : h3;
    __half*     yl = (z == 0) ? l0 : (z == 1) ? l1 : (z == 2) ? l2 : l3;
    int i = blockIdx.x * blockDim.x + threadIdx.x;
    int stride = gridDim.x * blockDim.x;
    for (; i < n4; i += stride) {
        float4 v = ((const float4*)x)[i];
        uint2 h, l;
        split2h(v.x, v.y, h.x, l.x);
        split2h(v.z, v.w, h.y, l.y);
        ((uint2*)yh)[i] = h;
        ((uint2*)yl)[i] = l;
    }
}

// ---------------------------------------------------------------------------
// GEMM: C[8192,1024] = A @ W^T + bias — fp16 2-pass, all-fp16 inputs,
// register-prefetch double buffer (R12 winner).
// Epilogue mode = base_mode + z:
//   0: fp32 out   1: fp16 scaled log2e/8 [Q]   2: fp16 [K]   3: fp16 [V]
// ---------------------------------------------------------------------------
#define GT_B    18432
#define GSTG_B  (3 * GT_B)
#define GSM_B   (2 * GSTG_B)         // 110592

#define QSCALE  0.18033688f   // 0.125 * log2(e)

__global__ __launch_bounds__(256, 1)
void gemm_f16(const __half* __restrict__ A0, const __half* __restrict__ Wh0,
              const __half* __restrict__ Wl0, const float* __restrict__ b0_,
              void* O0a,
              const __half* __restrict__ A1, const __half* __restrict__ Wh1,
              const __half* __restrict__ Wl1, const float* __restrict__ b1_,
              void* O1a,
              const __half* __restrict__ A2, const __half* __restrict__ Wh2,
              const __half* __restrict__ Wl2, const float* __restrict__ b2_,
              void* O2a,
              int base_mode)
{
    extern __shared__ char sm[];
    const uint32_t s0 = smem_u32(sm);

    const int z = blockIdx.z;
    const __half* A    = (z == 0) ? A0  : (z == 1) ? A1  : A2;
    const __half* Wh   = (z == 0) ? Wh0 : (z == 1) ? Wh1 : Wh2;
    const __half* Wl   = (z == 0) ? Wl0 : (z == 1) ? Wl1 : Wl2;
    const float*  bias = (z == 0) ? b0_ : (z == 1) ? b1_ : b2_;
    void* Oa = (z == 0) ? O0a : (z == 1) ? O1a : O2a;
    const int mode = base_mode + z;

    const int tid  = threadIdx.x;
    const int lane = tid & 31;
    const int wid  = tid >> 5;
    const int bm = blockIdx.y * 128;
    const int bn = blockIdx.x * 128;
    const int wm = (wid >> 2) * 64;
    const int wn = (wid & 3) * 32;

    float acc[4][4][4];
#pragma unroll
    for (int i = 0; i < 4; i++)
#pragma unroll
        for (int j = 0; j < 4; j++)
#pragma unroll
            for (int q = 0; q < 4; q++) acc[i][j][q] = 0.f;

    const uint32_t offA = (uint32_t)(lane & 15) * 144 + (uint32_t)(lane >> 4) * 16;
    const uint32_t offB = (uint32_t)((lane & 7) + ((lane >> 4) & 1) * 8) * 144
                        + (uint32_t)((lane >> 3) & 1) * 16;

    uint4 aw[4], whw[4], wlw[4];
#pragma unroll
    for (int j = 0; j < 4; j++) {
        int c = tid + j * 256;
        int row = c >> 3, seg = c & 7;
        aw[j]  = *(const uint4*)(A  + (size_t)(bm + row) * D_MODEL + seg * 8);
        whw[j] = *(const uint4*)(Wh + (size_t)(bn + row) * D_MODEL + seg * 8);
        wlw[j] = *(const uint4*)(Wl + (size_t)(bn + row) * D_MODEL + seg * 8);
    }
    {
        char* stg = sm;
#pragma unroll
        for (int j = 0; j < 4; j++) {
            int c = tid + j * 256;
            int row = c >> 3, seg = c & 7;
            uint32_t ad = (uint32_t)(row * 144 + seg * 16);
            *(uint4*)(stg + 0 * GT_B + ad) = aw[j];
            *(uint4*)(stg + 1 * GT_B + ad) = whw[j];
            *(uint4*)(stg + 2 * GT_B + ad) = wlw[j];
        }
    }
    __syncthreads();

    for (int kt = 0; kt < 16; kt++) {
        if (kt < 15) {
            const int k0 = (kt + 1) * 64;
#pragma unroll
            for (int j = 0; j < 4; j++) {
                int c = tid + j * 256;
                int row = c >> 3, seg = c & 7;
                aw[j]  = *(const uint4*)(A  + (size_t)(bm + row) * D_MODEL + k0 + seg * 8);
                whw[j] = *(const uint4*)(Wh + (size_t)(bn + row) * D_MODEL + k0 + seg * 8);
                wlw[j] = *(const uint4*)(Wl + (size_t)(bn + row) * D_MODEL + k0 + seg * 8);
            }
        }

        const uint32_t sb  = s0 + (uint32_t)(kt & 1) * GSTG_B;
        const uint32_t sA  = sb;
        const uint32_t sWh = sb + 1 * GT_B;
        const uint32_t sWl = sb + 2 * GT_B;

#pragma unroll
        for (int ks = 0; ks < 4; ks++) {
            uint32_t ah[4][4], wh[2][4], wl[2][4];
            const uint32_t ka = (uint32_t)ks * 32;
#pragma unroll
            for (int mt = 0; mt < 4; mt++) {
                uint32_t ra = (uint32_t)((wm + mt * 16) * 144) + offA + ka;
                ldm_x4(ah[mt], sA + ra);
            }
#pragma unroll
            for (int p = 0; p < 2; p++) {
                uint32_t rb = (uint32_t)((wn + p * 16) * 144) + offB + ka;
                ldm_x4(wh[p], sWh + rb);
                ldm_x4(wl[p], sWl + rb);
            }
#pragma unroll
            for (int mt = 0; mt < 4; mt++)
#pragma unroll
                for (int nt = 0; nt < 4; nt++) {
                    uint32_t h0 = wh[nt >> 1][(nt & 1) * 2];
                    uint32_t h1 = wh[nt >> 1][(nt & 1) * 2 + 1];
                    uint32_t l0 = wl[nt >> 1][(nt & 1) * 2];
                    uint32_t l1 = wl[nt >> 1][(nt & 1) * 2 + 1];
                    mma16816h(acc[mt][nt], ah[mt], h0, h1);
                    mma16816h(acc[mt][nt], ah[mt], l0, l1);
                }
        }

        if (kt < 15) {
            char* stg = sm + ((kt + 1) & 1) * GSTG_B;
#pragma unroll
            for (int j = 0; j < 4; j++) {
                int c = tid + j * 256;
                int row = c >> 3, seg = c & 7;
                uint32_t ad = (uint32_t)(row * 144 + seg * 16);
                *(uint4*)(stg + 0 * GT_B + ad) = aw[j];
                *(uint4*)(stg + 1 * GT_B + ad) = whw[j];
                *(uint4*)(stg + 2 * GT_B + ad) = wlw[j];
            }
        }
        __syncthreads();
    }

#pragma unroll
    for (int mt = 0; mt < 4; mt++) {
        int row0 = bm + wm + mt * 16 + (lane >> 2);
#pragma unroll
        for (int nt = 0; nt < 4; nt++) {
            int col = bn + wn + nt * 8 + (lane & 3) * 2;
            float2 b2 = *(const float2*)&bias[col];
            float c0 = acc[mt][nt][0] + b2.x, c1 = acc[mt][nt][1] + b2.y;
            float c2 = acc[mt][nt][2] + b2.x, c3 = acc[mt][nt][3] + b2.y;
            size_t i0 = (size_t)row0 * D_MODEL + col;
            size_t i1 = (size_t)(row0 + 8) * D_MODEL + col;
            if (mode == 0) {
                *(float2*)((float*)Oa + i0) = make_float2(c0, c1);
                *(float2*)((float*)Oa + i1) = make_float2(c2, c3);
            } else if (mode == 1) {       // Q: fp16 scaled log2e/8
                *(uint32_t*)((__half*)Oa + i0) = pack2h(c0 * QSCALE, c1 * QSCALE);
                *(uint32_t*)((__half*)Oa + i1) = pack2h(c2 * QSCALE, c3 * QSCALE);
            } else {                       // K / V: plain fp16
                *(uint32_t*)((__half*)Oa + i0) = pack2h(c0, c1);
                *(uint32_t*)((__half*)Oa + i1) = pack2h(c2, c3);
            }
        }
    }
}

// ---------------------------------------------------------------------------
// Flash attention — R12 pipeline, QK now 1-pass (K single fp16), PV 1-pass.
// 128 thr, 4 warps x 32 q-rows, BN=64 KV tile, cp.async 2-stage (K|V),
// exp2-domain softmax. smem: Q[128][72] + 2 x (K|V)[64][72] = 55.3 KB.
// ---------------------------------------------------------------------------
#define AQ    0
#define AKV0  18432
#define AT    9216
#define AST   (2 * AT)                // K | V stage = 18432
#define A_SMEM (AKV0 + 2 * AST)       // 55296

__global__ __launch_bounds__(128)
void attn_mma(const __half* __restrict__ Qp, const __half* __restrict__ Kp_,
              const __half* __restrict__ Vp, __half* __restrict__ Og)
{
    extern __shared__ char sm[];
    const uint32_t s0 = smem_u32(sm);

    const int tid  = threadIdx.x;
    const int lane = tid & 31;
    const int wid  = tid >> 5;
    const int qt = blockIdx.x;
    const int bh = blockIdx.y;
    const int b = bh >> 4, h = bh & 15;

    const size_t tok0 = (size_t)b * SEQ + qt * 128;
    const __half* Qb = Qp  + tok0 * D_MODEL + h * 64;
    const __half* Kb = Kp_ + (size_t)b * SEQ * D_MODEL + h * 64;
    const __half* Vb = Vp  + (size_t)b * SEQ * D_MODEL + h * 64;

    const uint32_t laneA = (uint32_t)(((lane >> 3) & 1) * 8 + (lane & 7)) * 144
                         + (uint32_t)(lane >> 4) * 16;
    const uint32_t laneB = (uint32_t)((lane >> 4) * 8 + (lane & 7)) * 144
                         + (uint32_t)((lane >> 3) & 1) * 16;
    const uint32_t wq = (uint32_t)wid * 32 * 144;

    auto issue_kv = [&](int kt) {
        const uint32_t sb = s0 + AKV0 + (uint32_t)(kt & 1) * AST;
        const size_t rb = (size_t)kt * 64 * D_MODEL;
#pragma unroll
        for (int j = 0; j < 4; j++) {
            int c = tid + j * 128;
            int row = c >> 3, seg = c & 7;
            size_t go = rb + (size_t)row * D_MODEL + seg * 8;
            uint32_t ad = (uint32_t)(row * 144 + seg * 16);
            cp16(sb + 0 * AT + ad, Kb + go);
            cp16(sb + 1 * AT + ad, Vb + go);
        }
        cp_commit();
    };

#pragma unroll
    for (int j = 0; j < 8; j++) {
        int c = tid + j * 128;
        int row = c >> 3, seg = c & 7;
        *(uint4*)(sm + AQ + row * 144 + seg * 16) =
            *(const uint4*)(Qb + (size_t)row * D_MODEL + seg * 8);
    }
    issue_kv(0);
    issue_kv(1);

    float o[2][8][4];
#pragma unroll
    for (int mt = 0; mt < 2; mt++)
#pragma unroll
        for (int dn = 0; dn < 8; dn++)
#pragma unroll
            for (int q = 0; q < 4; q++) o[mt][dn][q] = 0.f;
    float mrow[4] = {-1e30f, -1e30f, -1e30f, -1e30f};
    float lrow[4] = {0.f, 0.f, 0.f, 0.f};

    for (int kt = 0; kt < SEQ / 64; kt++) {
        CP_WAIT(1);
        __syncthreads();

        const uint32_t kb = s0 + AKV0 + (uint32_t)(kt & 1) * AST;

        // ---- S = Q @ K^T (1-pass); scores in log2 domain
        float s[2][8][4];
#pragma unroll
        for (int mt = 0; mt < 2; mt++)
#pragma unroll
            for (int nt = 0; nt < 8; nt++)
#pragma unroll
                for (int q = 0; q < 4; q++) s[mt][nt][q] = 0.f;

#pragma unroll
        for (int k = 0; k < 4; k++) {
            uint32_t bhf[4][4];
#pragma unroll
            for (int np = 0; np < 4; np++) {
                uint32_t rbb = (uint32_t)(np * 16 * 144) + k * 32 + laneB;
                ldm_x4(bhf[np], kb + 0 * AT + rbb);
            }
#pragma unroll
            for (int mt = 0; mt < 2; mt++) {
                uint32_t ah[4];
                uint32_t ra = wq + (uint32_t)(mt * 16 * 144) + k * 32 + laneA;
                ldm_x4(ah, s0 + AQ + ra);
#pragma unroll
                for (int nt = 0; nt < 8; nt++) {
                    uint32_t h0 = bhf[nt >> 1][(nt & 1) * 2];
                    uint32_t h1 = bhf[nt >> 1][(nt & 1) * 2 + 1];
                    mma16816h(s[mt][nt], ah, h0, h1);
                }
            }
        }

        // ---- online softmax (exp2 domain)
        float corr[4];
#pragma unroll
        for (int rr = 0; rr < 4; rr++) {
            int mt = rr >> 1, c0 = (rr & 1) * 2;
            float mx = -1e30f;
#pragma unroll
            for (int nt = 0; nt < 8; nt++)
                mx = fmaxf(mx, fmaxf(s[mt][nt][c0], s[mt][nt][c0 + 1]));
            mx = fmaxf(mx, __shfl_xor_sync(0xffffffffu, mx, 1));
            mx = fmaxf(mx, __shfl_xor_sync(0xffffffffu, mx, 2));
            float mn = fmaxf(mrow[rr], mx);
            corr[rr] = exp2f(mrow[rr] - mn);
            mrow[rr] = mn;
            float rs = 0.f;
#pragma unroll
            for (int nt = 0; nt < 8; nt++) {
                float e0 = exp2f(s[mt][nt][c0] - mn);
                float e1 = exp2f(s[mt][nt][c0 + 1] - mn);
                s[mt][nt][c0] = e0; s[mt][nt][c0 + 1] = e1;
                rs += e0 + e1;
            }
            rs += __shfl_xor_sync(0xffffffffu, rs, 1);
            rs += __shfl_xor_sync(0xffffffffu, rs, 2);
            lrow[rr] = lrow[rr] * corr[rr] + rs;
        }
#pragma unroll
        for (int mt = 0; mt < 2; mt++)
#pragma unroll
            for (int dn = 0; dn < 8; dn++) {
                o[mt][dn][0] *= corr[mt * 2];
                o[mt][dn][1] *= corr[mt * 2];
                o[mt][dn][2] *= corr[mt * 2 + 1];
                o[mt][dn][3] *= corr[mt * 2 + 1];
            }

        // ---- O += P @ V (1-pass)
#pragma unroll
        for (int kk = 0; kk < 4; kk++) {
            uint32_t vhf[4][4];
#pragma unroll
            for (int dp = 0; dp < 4; dp++) {
                uint32_t rv = (uint32_t)(kk * 16 * 144) + dp * 32 + laneA;
                ldm_x4_t(vhf[dp], kb + 1 * AT + rv);
            }
#pragma unroll
            for (int mt = 0; mt < 2; mt++) {
                uint32_t ph[4];
                ph[0] = pack2h(s[mt][2 * kk][0],     s[mt][2 * kk][1]);
                ph[1] = pack2h(s[mt][2 * kk][2],     s[mt][2 * kk][3]);
                ph[2] = pack2h(s[mt][2 * kk + 1][0], s[mt][2 * kk + 1][1]);
                ph[3] = pack2h(s[mt][2 * kk + 1][2], s[mt][2 * kk + 1][3]);
#pragma unroll
                for (int dn = 0; dn < 8; dn++) {
                    uint32_t h0 = vhf[dn >> 1][(dn & 1) * 2];
                    uint32_t h1 = vhf[dn >> 1][(dn & 1) * 2 + 1];
                    mma16816h(o[mt][dn], ph, h0, h1);
                }
            }
        }

        __syncthreads();
        if (kt + 2 < SEQ / 64) issue_kv(kt + 2);
    }

    float inv[4];
#pragma unroll
    for (int rr = 0; rr < 4; rr++) inv[rr] = 1.f / lrow[rr];
#pragma unroll
    for (int mt = 0; mt < 2; mt++) {
        size_t row0 = tok0 + wid * 32 + mt * 16 + (lane >> 2);
#pragma unroll
        for (int dn = 0; dn < 8; dn++) {
            int col = h * 64 + dn * 8 + (lane & 3) * 2;
            *(uint32_t*)(Og + row0 * D_MODEL + col) =
                pack2h(o[mt][dn][0] * inv[mt * 2], o[mt][dn][1] * inv[mt * 2]);
            *(uint32_t*)(Og + (row0 + 8) * D_MODEL + col) =
                pack2h(o[mt][dn][2] * inv[mt * 2 + 1], o[mt][dn][3] * inv[mt * 2 + 1]);
        }
    }
}

// ---------------------------------------------------------------------------
extern "C" void kernel_launch(void* const* d_in, const int* in_sizes, int n_in,
                              void* d_out, int out_size)
{
    const float* q  = (const float*)d_in[0];
    const float* k  = (const float*)d_in[1];
    const float* v  = (const float*)d_in[2];
    const float* Wq = (const float*)d_in[3];
    const float* bq = (const float*)d_in[4];
    const float* Wk = (const float*)d_in[5];
    const float* bk = (const float*)d_in[6];
    const float* Wv = (const float*)d_in[7];
    const float* bv = (const float*)d_in[8];
    const float* Wo = (const float*)d_in[9];
    const float* bo = (const float*)d_in[10];
    float* out = (float*)d_out;

    __half *qin, *kin, *vin;
    __half *Wqh, *Wql, *Wkh, *Wkl, *Wvh, *Wvl, *Woh, *Wol;
    __half *Qp, *Kp, *Vp, *Att;
    cudaGetSymbolAddress((void**)&qin, g_qin);
    cudaGetSymbolAddress((void**)&kin, g_kin);
    cudaGetSymbolAddress((void**)&vin, g_vin);
    cudaGetSymbolAddress((void**)&Wqh, g_Wqh); cudaGetSymbolAddress((void**)&Wql, g_Wql);
    cudaGetSymbolAddress((void**)&Wkh, g_Wkh); cudaGetSymbolAddress((void**)&Wkl, g_Wkl);
    cudaGetSymbolAddress((void**)&Wvh, g_Wvh); cudaGetSymbolAddress((void**)&Wvl, g_Wvl);
    cudaGetSymbolAddress((void**)&Woh, g_Woh); cudaGetSymbolAddress((void**)&Wol, g_Wol);
    cudaGetSymbolAddress((void**)&Qp,  g_Qp);
    cudaGetSymbolAddress((void**)&Kp,  g_Kp);
    cudaGetSymbolAddress((void**)&Vp,  g_Vp);
    cudaGetSymbolAddress((void**)&Att, g_Att);

    cudaFuncSetAttribute(gemm_f16,
                         cudaFuncAttributeMaxDynamicSharedMemorySize, GSM_B);
    cudaFuncSetAttribute(attn_mma,
                         cudaFuncAttributeMaxDynamicSharedMemorySize, A_SMEM);

    cvt_f16<<<dim3(512, 1, 3), 256>>>(q, qin, k, kin, v, vin, (int)(ACT_N / 4));
    wsplit_f16<<<dim3(256, 1, 4), 256>>>(Wq, Wqh, Wql, Wk, Wkh, Wkl,
                                         Wv, Wvh, Wvl, Wo, Woh, Wol,
                                         (int)(W_N / 4));

    dim3 pgrid(D_MODEL / 128, NTOK / 128, 3);
    gemm_f16<<<pgrid, 256, GSM_B>>>(qin, Wqh, Wql, bq, Qp,
                                    kin, Wkh, Wkl, bk, Kp,
                                    vin, Wvh, Wvl, bv, Vp,
                                    1);

    attn_mma<<<dim3(SEQ / 128, BATCH * NHEAD), 128, A_SMEM>>>(Qp, Kp, Vp, Att);

    dim3 ogrid(D_MODEL / 128, NTOK / 128, 1);
    gemm_f16<<<ogrid, 256, GSM_B>>>(Att, Woh, Wol, bo, out,
                                    Att, Woh, Wol, bo, out,
                                    Att, Woh, Wol, bo, out,
                                    0);
}

// round 17
// speedup vs baseline: 1.5396x; 1.2728x over previous
#include <cuda_runtime.h>
#include <cuda_fp16.h>
#include <cstdint>

#define D_MODEL 1024
#define NHEAD   16
#define HDIM    64
#define BATCH   4
#define SEQ     2048
#define NTOK    (BATCH*SEQ)

#define ACT_N ((size_t)NTOK * D_MODEL)
#define W_N   ((size_t)D_MODEL * D_MODEL)

// Scratch (allocation-free per harness rules) — all fp16, all single precision
__device__ __half g_qin[ACT_N], g_kin[ACT_N], g_vin[ACT_N];
__device__ __half g_Wq16[W_N], g_Wk16[W_N], g_Wv16[W_N], g_Wo16[W_N];
__device__ __half g_Qp[ACT_N];                 // scaled by log2(e)/8
__device__ __half g_Kp[ACT_N];
__device__ __half g_Vp[ACT_N];
__device__ __half g_Att[ACT_N];

// ---------------------------------------------------------------------------
// helpers
// ---------------------------------------------------------------------------
__device__ __forceinline__ uint32_t smem_u32(const void* p) {
    uint32_t a;
    asm("{ .reg .u64 t; cvta.to.shared.u64 t, %1; cvt.u32.u64 %0, t; }"
        : "=r"(a) : "l"(p));
    return a;
}
__device__ __forceinline__ void ldm_x4(uint32_t r[4], uint32_t addr) {
    asm volatile("ldmatrix.sync.aligned.m8n8.x4.shared.b16 {%0,%1,%2,%3}, [%4];"
                 : "=r"(r[0]), "=r"(r[1]), "=r"(r[2]), "=r"(r[3]) : "r"(addr));
}
__device__ __forceinline__ void ldm_x4_t(uint32_t r[4], uint32_t addr) {
    asm volatile("ldmatrix.sync.aligned.m8n8.x4.trans.shared.b16 {%0,%1,%2,%3}, [%4];"
                 : "=r"(r[0]), "=r"(r[1]), "=r"(r[2]), "=r"(r[3]) : "r"(addr));
}
__device__ __forceinline__ void mma16816h(float c[4], const uint32_t a[4],
                                          uint32_t b0, uint32_t b1) {
    asm volatile(
        "mma.sync.aligned.m16n8k16.row.col.f32.f16.f16.f32 "
        "{%0,%1,%2,%3}, {%4,%5,%6,%7}, {%8,%9}, {%0,%1,%2,%3};"
        : "+f"(c[0]), "+f"(c[1]), "+f"(c[2]), "+f"(c[3])
        : "r"(a[0]), "r"(a[1]), "r"(a[2]), "r"(a[3]), "r"(b0), "r"(b1));
}
__device__ __forceinline__ uint32_t pack2h(float f0, float f1) {
    __half2 h = __floats2half2_rn(f0, f1);
    return *(uint32_t*)&h;
}
__device__ __forceinline__ void cp16(uint32_t dst, const void* src) {
    asm volatile("cp.async.cg.shared.global [%0], [%1], 16;"
                 :: "r"(dst), "l"(src) : "memory");
}
__device__ __forceinline__ void cp_commit() {
    asm volatile("cp.async.commit_group;" ::: "memory");
}
#define CP_WAIT(n) asm volatile("cp.async.wait_group %0;" :: "n"(n) : "memory")

// ------------------------- producer conversion kernels ----------------------
__global__ void cvt_f16(const float* __restrict__ x0, __half* __restrict__ y0,
                        const float* __restrict__ x1, __half* __restrict__ y1,
                        const float* __restrict__ x2, __half* __restrict__ y2,
                        int n4)
{
    const float* x = (blockIdx.z == 0) ? x0 : (blockIdx.z == 1) ? x1 : x2;
    __half*      y = (blockIdx.z == 0) ? y0 : (blockIdx.z == 1) ? y1 : y2;
    int i = blockIdx.x * blockDim.x + threadIdx.x;
    int stride = gridDim.x * blockDim.x;
    for (; i < n4; i += stride) {
        float4 v = ((const float4*)x)[i];
        uint2 r;
        r.x = pack2h(v.x, v.y);
        r.y = pack2h(v.z, v.w);
        ((uint2*)y)[i] = r;
    }
}

__global__ void wcvt_f16(const float* __restrict__ x0, __half* __restrict__ y0,
                         const float* __restrict__ x1, __half* __restrict__ y1,
                         const float* __restrict__ x2, __half* __restrict__ y2,
                         const float* __restrict__ x3, __half* __restrict__ y3,
                         int n4)
{
    int z = blockIdx.z;
    const float* x = (z == 0) ? x0 : (z == 1) ? x1 : (z == 2) ? x2 : x3;
    __half*      y = (z == 0) ? y0 : (z == 1) ? y1 : (z == 2) ? y2 : y3;
    int i = blockIdx.x * blockDim.x + threadIdx.x;
    int stride = gridDim.x * blockDim.x;
    for (; i < n4; i += stride) {
        float4 v = ((const float4*)x)[i];
        uint2 r;
        r.x = pack2h(v.x, v.y);
        r.y = pack2h(v.z, v.w);
        ((uint2*)y)[i] = r;
    }
}

// ---------------------------------------------------------------------------
// GEMM: C[8192,1024] = A @ W^T + bias — fp16 1-pass (A and W single fp16),
// register-prefetch double buffer. 128x128 tile, BK=64, 256 thr.
// Epilogue mode = base_mode + z:
//   0: fp32 out   1: fp16 scaled log2e/8 [Q]   2: fp16 [K]   3: fp16 [V]
// ---------------------------------------------------------------------------
#define GT_B    18432
#define GSTG_B  (2 * GT_B)           // A | W = 36864
#define GSM_B   (2 * GSTG_B)         // 73728

#define QSCALE  0.18033688f   // 0.125 * log2(e)

__global__ __launch_bounds__(256, 1)
void gemm_f16(const __half* __restrict__ A0, const __half* __restrict__ W0,
              const float* __restrict__ b0_, void* O0a,
              const __half* __restrict__ A1, const __half* __restrict__ W1,
              const float* __restrict__ b1_, void* O1a,
              const __half* __restrict__ A2, const __half* __restrict__ W2,
              const float* __restrict__ b2_, void* O2a,
              int base_mode)
{
    extern __shared__ char sm[];
    const uint32_t s0 = smem_u32(sm);

    const int z = blockIdx.z;
    const __half* A    = (z == 0) ? A0  : (z == 1) ? A1  : A2;
    const __half* W    = (z == 0) ? W0  : (z == 1) ? W1  : W2;
    const float*  bias = (z == 0) ? b0_ : (z == 1) ? b1_ : b2_;
    void* Oa = (z == 0) ? O0a : (z == 1) ? O1a : O2a;
    const int mode = base_mode + z;

    const int tid  = threadIdx.x;
    const int lane = tid & 31;
    const int wid  = tid >> 5;
    const int bm = blockIdx.y * 128;
    const int bn = blockIdx.x * 128;
    const int wm = (wid >> 2) * 64;
    const int wn = (wid & 3) * 32;

    float acc[4][4][4];
#pragma unroll
    for (int i = 0; i < 4; i++)
#pragma unroll
        for (int j = 0; j < 4; j++)
#pragma unroll
            for (int q = 0; q < 4; q++) acc[i][j][q] = 0.f;

    const uint32_t offA = (uint32_t)(lane & 15) * 144 + (uint32_t)(lane >> 4) * 16;
    const uint32_t offB = (uint32_t)((lane & 7) + ((lane >> 4) & 1) * 8) * 144
                        + (uint32_t)((lane >> 3) & 1) * 16;

    uint4 aw[4], ww[4];
#pragma unroll
    for (int j = 0; j < 4; j++) {
        int c = tid + j * 256;
        int row = c >> 3, seg = c & 7;
        aw[j] = *(const uint4*)(A + (size_t)(bm + row) * D_MODEL + seg * 8);
        ww[j] = *(const uint4*)(W + (size_t)(bn + row) * D_MODEL + seg * 8);
    }
    {
        char* stg = sm;
#pragma unroll
        for (int j = 0; j < 4; j++) {
            int c = tid + j * 256;
            int row = c >> 3, seg = c & 7;
            uint32_t ad = (uint32_t)(row * 144 + seg * 16);
            *(uint4*)(stg + 0 * GT_B + ad) = aw[j];
            *(uint4*)(stg + 1 * GT_B + ad) = ww[j];
        }
    }
    __syncthreads();

    for (int kt = 0; kt < 16; kt++) {
        if (kt < 15) {
            const int k0 = (kt + 1) * 64;
#pragma unroll
            for (int j = 0; j < 4; j++) {
                int c = tid + j * 256;
                int row = c >> 3, seg = c & 7;
                aw[j] = *(const uint4*)(A + (size_t)(bm + row) * D_MODEL + k0 + seg * 8);
                ww[j] = *(const uint4*)(W + (size_t)(bn + row) * D_MODEL + k0 + seg * 8);
            }
        }

        const uint32_t sb = s0 + (uint32_t)(kt & 1) * GSTG_B;
        const uint32_t sA = sb;
        const uint32_t sW = sb + 1 * GT_B;

#pragma unroll
        for (int ks = 0; ks < 4; ks++) {
            uint32_t ah[4][4], wh[2][4];
            const uint32_t ka = (uint32_t)ks * 32;
#pragma unroll
            for (int mt = 0; mt < 4; mt++) {
                uint32_t ra = (uint32_t)((wm + mt * 16) * 144) + offA + ka;
                ldm_x4(ah[mt], sA + ra);
            }
#pragma unroll
            for (int p = 0; p < 2; p++) {
                uint32_t rb = (uint32_t)((wn + p * 16) * 144) + offB + ka;
                ldm_x4(wh[p], sW + rb);
            }
#pragma unroll
            for (int mt = 0; mt < 4; mt++)
#pragma unroll
                for (int nt = 0; nt < 4; nt++) {
                    uint32_t h0 = wh[nt >> 1][(nt & 1) * 2];
                    uint32_t h1 = wh[nt >> 1][(nt & 1) * 2 + 1];
                    mma16816h(acc[mt][nt], ah[mt], h0, h1);
                }
        }

        if (kt < 15) {
            char* stg = sm + ((kt + 1) & 1) * GSTG_B;
#pragma unroll
            for (int j = 0; j < 4; j++) {
                int c = tid + j * 256;
                int row = c >> 3, seg = c & 7;
                uint32_t ad = (uint32_t)(row * 144 + seg * 16);
                *(uint4*)(stg + 0 * GT_B + ad) = aw[j];
                *(uint4*)(stg + 1 * GT_B + ad) = ww[j];
            }
        }
        __syncthreads();
    }

#pragma unroll
    for (int mt = 0; mt < 4; mt++) {
        int row0 = bm + wm + mt * 16 + (lane >> 2);
#pragma unroll
        for (int nt = 0; nt < 4; nt++) {
            int col = bn + wn + nt * 8 + (lane & 3) * 2;
            float2 b2 = *(const float2*)&bias[col];
            float c0 = acc[mt][nt][0] + b2.x, c1 = acc[mt][nt][1] + b2.y;
            float c2 = acc[mt][nt][2] + b2.x, c3 = acc[mt][nt][3] + b2.y;
            size_t i0 = (size_t)row0 * D_MODEL + col;
            size_t i1 = (size_t)(row0 + 8) * D_MODEL + col;
            if (mode == 0) {
                *(float2*)((float*)Oa + i0) = make_float2(c0, c1);
                *(float2*)((float*)Oa + i1) = make_float2(c2, c3);
            } else if (mode == 1) {       // Q: fp16 scaled log2e/8
                *(uint32_t*)((__half*)Oa + i0) = pack2h(c0 * QSCALE, c1 * QSCALE);
                *(uint32_t*)((__half*)Oa + i1) = pack2h(c2 * QSCALE, c3 * QSCALE);
            } else {                       // K / V: plain fp16
                *(uint32_t*)((__half*)Oa + i0) = pack2h(c0, c1);
                *(uint32_t*)((__half*)Oa + i1) = pack2h(c2, c3);
            }
        }
    }
}

// ---------------------------------------------------------------------------
// Flash attention — R16 kernel (frozen): QK 1-pass, PV 1-pass, cp.async
// 2-stage (K|V), exp2-domain softmax. 128 thr, 4 warps x 32 q-rows.
// ---------------------------------------------------------------------------
#define AQ    0
#define AKV0  18432
#define AT    9216
#define AST   (2 * AT)
#define A_SMEM (AKV0 + 2 * AST)       // 55296

__global__ __launch_bounds__(128)
void attn_mma(const __half* __restrict__ Qp, const __half* __restrict__ Kp_,
              const __half* __restrict__ Vp, __half* __restrict__ Og)
{
    extern __shared__ char sm[];
    const uint32_t s0 = smem_u32(sm);

    const int tid  = threadIdx.x;
    const int lane = tid & 31;
    const int wid  = tid >> 5;
    const int qt = blockIdx.x;
    const int bh = blockIdx.y;
    const int b = bh >> 4, h = bh & 15;

    const size_t tok0 = (size_t)b * SEQ + qt * 128;
    const __half* Qb = Qp  + tok0 * D_MODEL + h * 64;
    const __half* Kb = Kp_ + (size_t)b * SEQ * D_MODEL + h * 64;
    const __half* Vb = Vp  + (size_t)b * SEQ * D_MODEL + h * 64;

    const uint32_t laneA = (uint32_t)(((lane >> 3) & 1) * 8 + (lane & 7)) * 144
                         + (uint32_t)(lane >> 4) * 16;
    const uint32_t laneB = (uint32_t)((lane >> 4) * 8 + (lane & 7)) * 144
                         + (uint32_t)((lane >> 3) & 1) * 16;
    const uint32_t wq = (uint32_t)wid * 32 * 144;

    auto issue_kv = [&](int kt) {
        const uint32_t sb = s0 + AKV0 + (uint32_t)(kt & 1) * AST;
        const size_t rb = (size_t)kt * 64 * D_MODEL;
#pragma unroll
        for (int j = 0; j < 4; j++) {
            int c = tid + j * 128;
            int row = c >> 3, seg = c & 7;
            size_t go = rb + (size_t)row * D_MODEL + seg * 8;
            uint32_t ad = (uint32_t)(row * 144 + seg * 16);
            cp16(sb + 0 * AT + ad, Kb + go);
            cp16(sb + 1 * AT + ad, Vb + go);
        }
        cp_commit();
    };

#pragma unroll
    for (int j = 0; j < 8; j++) {
        int c = tid + j * 128;
        int row = c >> 3, seg = c & 7;
        *(uint4*)(sm + AQ + row * 144 + seg * 16) =
            *(const uint4*)(Qb + (size_t)row * D_MODEL + seg * 8);
    }
    issue_kv(0);
    issue_kv(1);

    float o[2][8][4];
#pragma unroll
    for (int mt = 0; mt < 2; mt++)
#pragma unroll
        for (int dn = 0; dn < 8; dn++)
#pragma unroll
            for (int q = 0; q < 4; q++) o[mt][dn][q] = 0.f;
    float mrow[4] = {-1e30f, -1e30f, -1e30f, -1e30f};
    float lrow[4] = {0.f, 0.f, 0.f, 0.f};

    for (int kt = 0; kt < SEQ / 64; kt++) {
        CP_WAIT(1);
        __syncthreads();

        const uint32_t kb = s0 + AKV0 + (uint32_t)(kt & 1) * AST;

        float s[2][8][4];
#pragma unroll
        for (int mt = 0; mt < 2; mt++)
#pragma unroll
            for (int nt = 0; nt < 8; nt++)
#pragma unroll
                for (int q = 0; q < 4; q++) s[mt][nt][q] = 0.f;

#pragma unroll
        for (int k = 0; k < 4; k++) {
            uint32_t bhf[4][4];
#pragma unroll
            for (int np = 0; np < 4; np++) {
                uint32_t rbb = (uint32_t)(np * 16 * 144) + k * 32 + laneB;
                ldm_x4(bhf[np], kb + 0 * AT + rbb);
            }
#pragma unroll
            for (int mt = 0; mt < 2; mt++) {
                uint32_t ah[4];
                uint32_t ra = wq + (uint32_t)(mt * 16 * 144) + k * 32 + laneA;
                ldm_x4(ah, s0 + AQ + ra);
#pragma unroll
                for (int nt = 0; nt < 8; nt++) {
                    uint32_t h0 = bhf[nt >> 1][(nt & 1) * 2];
                    uint32_t h1 = bhf[nt >> 1][(nt & 1) * 2 + 1];
                    mma16816h(s[mt][nt], ah, h0, h1);
                }
            }
        }

        float corr[4];
#pragma unroll
        for (int rr = 0; rr < 4; rr++) {
            int mt = rr >> 1, c0 = (rr & 1) * 2;
            float mx = -1e30f;
#pragma unroll
            for (int nt = 0; nt < 8; nt++)
                mx = fmaxf(mx, fmaxf(s[mt][nt][c0], s[mt][nt][c0 + 1]));
            mx = fmaxf(mx, __shfl_xor_sync(0xffffffffu, mx, 1));
            mx = fmaxf(mx, __shfl_xor_sync(0xffffffffu, mx, 2));
            float mn = fmaxf(mrow[rr], mx);
            corr[rr] = exp2f(mrow[rr] - mn);
            mrow[rr] = mn;
            float rs = 0.f;
#pragma unroll
            for (int nt = 0; nt < 8; nt++) {
                float e0 = exp2f(s[mt][nt][c0] - mn);
                float e1 = exp2f(s[mt][nt][c0 + 1] - mn);
                s[mt][nt][c0] = e0; s[mt][nt][c0 + 1] = e1;
                rs += e0 + e1;
            }
            rs += __shfl_xor_sync(0xffffffffu, rs, 1);
            rs += __shfl_xor_sync(0xffffffffu, rs, 2);
            lrow[rr] = lrow[rr] * corr[rr] + rs;
        }
#pragma unroll
        for (int mt = 0; mt < 2; mt++)
#pragma unroll
            for (int dn = 0; dn < 8; dn++) {
                o[mt][dn][0] *= corr[mt * 2];
                o[mt][dn][1] *= corr[mt * 2];
                o[mt][dn][2] *= corr[mt * 2 + 1];
                o[mt][dn][3] *= corr[mt * 2 + 1];
            }

#pragma unroll
        for (int kk = 0; kk < 4; kk++) {
            uint32_t vhf[4][4];
#pragma unroll
            for (int dp = 0; dp < 4; dp++) {
                uint32_t rv = (uint32_t)(kk * 16 * 144) + dp * 32 + laneA;
                ldm_x4_t(vhf[dp], kb + 1 * AT + rv);
            }
#pragma unroll
            for (int mt = 0; mt < 2; mt++) {
                uint32_t ph[4];
                ph[0] = pack2h(s[mt][2 * kk][0],     s[mt][2 * kk][1]);
                ph[1] = pack2h(s[mt][2 * kk][2],     s[mt][2 * kk][3]);
                ph[2] = pack2h(s[mt][2 * kk + 1][0], s[mt][2 * kk + 1][1]);
                ph[3] = pack2h(s[mt][2 * kk + 1][2], s[mt][2 * kk + 1][3]);
#pragma unroll
                for (int dn = 0; dn < 8; dn++) {
                    uint32_t h0 = vhf[dn >> 1][(dn & 1) * 2];
                    uint32_t h1 = vhf[dn >> 1][(dn & 1) * 2 + 1];
                    mma16816h(o[mt][dn], ph, h0, h1);
                }
            }
        }

        __syncthreads();
        if (kt + 2 < SEQ / 64) issue_kv(kt + 2);
    }

    float inv[4];
#pragma unroll
    for (int rr = 0; rr < 4; rr++) inv[rr] = 1.f / lrow[rr];
#pragma unroll
    for (int mt = 0; mt < 2; mt++) {
        size_t row0 = tok0 + wid * 32 + mt * 16 + (lane >> 2);
#pragma unroll
        for (int dn = 0; dn < 8; dn++) {
            int col = h * 64 + dn * 8 + (lane & 3) * 2;
            *(uint32_t*)(Og + row0 * D_MODEL + col) =
                pack2h(o[mt][dn][0] * inv[mt * 2], o[mt][dn][1] * inv[mt * 2]);
            *(uint32_t*)(Og + (row0 + 8) * D_MODEL + col) =
                pack2h(o[mt][dn][2] * inv[mt * 2 + 1], o[mt][dn][3] * inv[mt * 2 + 1]);
        }
    }
}

// ---------------------------------------------------------------------------
extern "C" void kernel_launch(void* const* d_in, const int* in_sizes, int n_in,
                              void* d_out, int out_size)
{
    const float* q  = (const float*)d_in[0];
    const float* k  = (const float*)d_in[1];
    const float* v  = (const float*)d_in[2];
    const float* Wq = (const float*)d_in[3];
    const float* bq = (const float*)d_in[4];
    const float* Wk = (const float*)d_in[5];
    const float* bk = (const float*)d_in[6];
    const float* Wv = (const float*)d_in[7];
    const float* bv = (const float*)d_in[8];
    const float* Wo = (const float*)d_in[9];
    const float* bo = (const float*)d_in[10];
    float* out = (float*)d_out;

    __half *qin, *kin, *vin;
    __half *Wq16, *Wk16, *Wv16, *Wo16;
    __half *Qp, *Kp, *Vp, *Att;
    cudaGetSymbolAddress((void**)&qin, g_qin);
    cudaGetSymbolAddress((void**)&kin, g_kin);
    cudaGetSymbolAddress((void**)&vin, g_vin);
    cudaGetSymbolAddress((void**)&Wq16, g_Wq16);
    cudaGetSymbolAddress((void**)&Wk16, g_Wk16);
    cudaGetSymbolAddress((void**)&Wv16, g_Wv16);
    cudaGetSymbolAddress((void**)&Wo16, g_Wo16);
    cudaGetSymbolAddress((void**)&Qp,  g_Qp);
    cudaGetSymbolAddress((void**)&Kp,  g_Kp);
    cudaGetSymbolAddress((void**)&Vp,  g_Vp);
    cudaGetSymbolAddress((void**)&Att, g_Att);

    cudaFuncSetAttribute(gemm_f16,
                         cudaFuncAttributeMaxDynamicSharedMemorySize, GSM_B);
    cudaFuncSetAttribute(attn_mma,
                         cudaFuncAttributeMaxDynamicSharedMemorySize, A_SMEM);

    cvt_f16<<<dim3(512, 1, 3), 256>>>(q, qin, k, kin, v, vin, (int)(ACT_N / 4));
    wcvt_f16<<<dim3(256, 1, 4), 256>>>(Wq, Wq16, Wk, Wk16,
                                       Wv, Wv16, Wo, Wo16, (int)(W_N / 4));

    dim3 pgrid(D_MODEL / 128, NTOK / 128, 3);
    gemm_f16<<<pgrid, 256, GSM_B>>>(qin, Wq16, bq, Qp,
                                    kin, Wk16, bk, Kp,
                                    vin, Wv16, bv, Vp,
                                    1);

    attn_mma<<<dim3(SEQ / 128, BATCH * NHEAD), 128, A_SMEM>>>(Qp, Kp, Vp, Att);

    dim3 ogrid(D_MODEL / 128, NTOK / 128, 1);
    gemm_f16<<<ogrid, 256, GSM_B>>>(Att, Wo16, bo, out,
                                    Att, Wo16, bo, out,
                                    Att, Wo16, bo, out,
                                    0);
}